// round 1
// baseline (speedup 1.0000x reference)
#include <cuda_runtime.h>
#include <math.h>

#define BB   1024
#define NSEQ 60
#define FF   1024
#define NN   120   // 2*NSEQ

// Output layout (flattened tuple, fp32):
// x(B,2,2048) o1(B,2,1024) o2 h1 h2 ATT1(B,60,1) ATT2 att11(B,60) att22 att12 att21
#define OFF_X    0ull
#define OFF_O1   4194304ull
#define OFF_O2   6291456ull
#define OFF_H1   8388608ull
#define OFF_H2   10485760ull
#define OFF_ATT1 12582912ull
#define OFF_ATT2 12644352ull
#define OFF_A11  12705792ull
#define OFF_A22  12767232ull
#define OFF_A12  12828672ull
#define OFF_A21  12890112ull

// Scratch: 4 selected rows per batch (j=0,1 from x1; j=2,3 from x2)
static __device__ float g_th[4096 * 1024];  // tanh(h), row (b*4+j)
static __device__ float g_qm[4096 * 1024];  // qm,      row (b*4+j)

typedef unsigned long long ull;

__device__ __forceinline__ float dot4(float4 a, float4 b) {
    return a.x * b.x + a.y * b.y + a.z * b.z + a.w * b.w;
}
__device__ __forceinline__ ull pk2(float a, float b) {
    ull r;
    asm("mov.b64 %0, {%1, %2};" : "=l"(r) : "f"(a), "f"(b));
    return r;
}
__device__ __forceinline__ void fma2(ull& c, ull a, ull b) {
    asm("fma.rn.f32x2 %0, %1, %2, %0;" : "+l"(c) : "l"(a), "l"(b));
}
__device__ __forceinline__ void upk2(ull c, float& lo, float& hi) {
    asm("mov.b64 {%0, %1}, %2;" : "=f"(lo), "=f"(hi) : "l"(c));
}

// ---------------------------------------------------------------------------
// K1: logits = x @ fc_w.T ; argmax over N per class ; gather h ; write h + tanh(h)
// grid (B, 2), 256 threads
// ---------------------------------------------------------------------------
__global__ __launch_bounds__(256) void k_select(
    const float* __restrict__ x1, const float* __restrict__ x2,
    const float* __restrict__ fc_w, float* __restrict__ out)
{
    const int b = blockIdx.x;
    const int which = blockIdx.y;
    const float* x = which ? x2 : x1;
    const float4* x4 = (const float4*)(x + (size_t)b * NSEQ * FF);

    const int tid = threadIdx.x;
    const int w = tid >> 5, lane = tid & 31;

    __shared__ float s_log[2][64];
    __shared__ int s_idx[2];

    // fc_w slices for this lane's 32 f-positions, both classes, in registers
    const float4* fw4 = (const float4*)fc_w;
    float4 w0[8], w1[8];
#pragma unroll
    for (int i = 0; i < 8; i++) {
        w0[i] = fw4[lane + 32 * i];
        w1[i] = fw4[256 + lane + 32 * i];
    }

    // warp-per-row logits
    for (int n = w; n < NSEQ; n += 8) {
        const float4* row = x4 + n * 256;
        float p0 = 0.f, p1 = 0.f;
#pragma unroll
        for (int i = 0; i < 8; i++) {
            float4 v = row[lane + 32 * i];
            p0 += dot4(v, w0[i]);
            p1 += dot4(v, w1[i]);
        }
#pragma unroll
        for (int off = 16; off; off >>= 1) {
            p0 += __shfl_down_sync(0xffffffffu, p0, off);
            p1 += __shfl_down_sync(0xffffffffu, p1, off);
        }
        if (lane == 0) { s_log[0][n] = p0; s_log[1][n] = p1; }
    }
    __syncthreads();

    // argmax (fc_b is a per-class constant: doesn't change argmax over n)
    if (tid < 2) {
        float best = s_log[tid][0];
        int bi = 0;
        for (int n = 1; n < NSEQ; n++) {
            float v = s_log[tid][n];
            if (v > best) { best = v; bi = n; }
        }
        s_idx[tid] = bi;
    }
    __syncthreads();

    const int i0 = s_idx[0], i1 = s_idx[1];
    float4* h4 = (float4*)(out + (which ? OFF_H2 : OFF_H1) + (size_t)b * 2 * FF);
    float4* th4 = (float4*)(g_th + ((size_t)b * 4 + which * 2) * FF);

    float4 v = x4[i0 * 256 + tid];
    h4[tid] = v;
    th4[tid] = make_float4(tanhf(v.x), tanhf(v.y), tanhf(v.z), tanhf(v.w));
    v = x4[i1 * 256 + tid];
    h4[256 + tid] = v;
    th4[256 + tid] = make_float4(tanhf(v.x), tanhf(v.y), tanhf(v.z), tanhf(v.w));
}

// ---------------------------------------------------------------------------
// K2: g_qm[m,:] = g_th[m,:] @ q_w.T + q_b   (M=4096, N=1024, K=1024, fp32)
// BM=128, BN=64, BK=16, 256 threads, 8x4 thread tile, packed f32x2 FMA
// grid (16, 32)
// ---------------------------------------------------------------------------
__global__ __launch_bounds__(256) void k_qm(
    const float* __restrict__ qw, const float* __restrict__ qb)
{
    __shared__ float As[16][128];
    __shared__ float Bs[16][64];

    const int n0 = blockIdx.x * 64;
    const int m0 = blockIdx.y * 128;
    const int tid = threadIdx.x;
    const int tm = tid >> 4;   // 0..15 -> 8 m-rows
    const int tn = tid & 15;   // 0..15 -> 4 n-cols

    ull c2[4][4];
#pragma unroll
    for (int i = 0; i < 4; i++)
#pragma unroll
        for (int j = 0; j < 4; j++) c2[i][j] = 0ull;

    for (int k0 = 0; k0 < 1024; k0 += 16) {
        // load A tile (128 rows x 16 k), store transposed As[k][m]
#pragma unroll
        for (int q = 0; q < 2; q++) {
            int idx = tid * 2 + q;
            int row = idx >> 2, kk4 = idx & 3;
            float4 v = *(const float4*)(g_th + (size_t)(m0 + row) * 1024 + k0 + kk4 * 4);
            As[kk4 * 4 + 0][row] = v.x;
            As[kk4 * 4 + 1][row] = v.y;
            As[kk4 * 4 + 2][row] = v.z;
            As[kk4 * 4 + 3][row] = v.w;
        }
        {
            int row = tid >> 2, kk4 = tid & 3;
            float4 v = *(const float4*)(qw + (size_t)(n0 + row) * 1024 + k0 + kk4 * 4);
            Bs[kk4 * 4 + 0][row] = v.x;
            Bs[kk4 * 4 + 1][row] = v.y;
            Bs[kk4 * 4 + 2][row] = v.z;
            Bs[kk4 * 4 + 3][row] = v.w;
        }
        __syncthreads();

#pragma unroll
        for (int kk = 0; kk < 16; kk++) {
            float4 a01 = *(const float4*)&As[kk][tm * 8];
            float4 a23 = *(const float4*)&As[kk][tm * 8 + 4];
            float4 bv  = *(const float4*)&Bs[kk][tn * 4];
            ull a2[4] = { pk2(a01.x, a01.y), pk2(a01.z, a01.w),
                          pk2(a23.x, a23.y), pk2(a23.z, a23.w) };
            ull b2[4] = { pk2(bv.x, bv.x), pk2(bv.y, bv.y),
                          pk2(bv.z, bv.z), pk2(bv.w, bv.w) };
#pragma unroll
            for (int mp = 0; mp < 4; mp++)
#pragma unroll
                for (int n = 0; n < 4; n++) fma2(c2[mp][n], a2[mp], b2[n]);
        }
        __syncthreads();
    }

    float4 qb4 = *(const float4*)(qb + n0 + tn * 4);
#pragma unroll
    for (int mp = 0; mp < 4; mp++) {
        float lo0, hi0, lo1, hi1, lo2, hi2, lo3, hi3;
        upk2(c2[mp][0], lo0, hi0);
        upk2(c2[mp][1], lo1, hi1);
        upk2(c2[mp][2], lo2, hi2);
        upk2(c2[mp][3], lo3, hi3);
        int m = m0 + tm * 8 + mp * 2;
        float4 r0 = make_float4(lo0 + qb4.x, lo1 + qb4.y, lo2 + qb4.z, lo3 + qb4.w);
        float4 r1 = make_float4(hi0 + qb4.x, hi1 + qb4.y, hi2 + qb4.z, hi3 + qb4.w);
        *(float4*)(g_qm + (size_t)m * 1024 + n0 + tn * 4) = r0;
        *(float4*)(g_qm + (size_t)(m + 1) * 1024 + n0 + tn * 4) = r1;
    }
}

// ---------------------------------------------------------------------------
// K3: fused attention with online softmax — single pass over L = [x1;x2]
// grid (B), 256 threads. Thread t owns f in [4t, 4t+4). j=0,1: attend1 c=0,1;
// j=2,3: attend2 c=0,1.
// ---------------------------------------------------------------------------
__global__ __launch_bounds__(256) void k_attend(
    const float* __restrict__ x1, const float* __restrict__ x2,
    float* __restrict__ out)
{
    const int b = blockIdx.x;
    const int tid = threadIdx.x;
    const int w = tid >> 5, lane = tid & 31;

    __shared__ float s_s[NN][4];     // raw (scaled) scores, kept for A outputs
    __shared__ float s_w[4][4];      // [r][j] exp weights for current batch
    __shared__ float s_alpha[4];
    __shared__ float s_red[8][16];   // per-warp partials [warp][r*4+j]
    __shared__ float s_m[4], s_l[4];

    const float4* x14 = (const float4*)(x1 + (size_t)b * NSEQ * FF);
    const float4* x24 = (const float4*)(x2 + (size_t)b * NSEQ * FF);
    const float4* qmg = (const float4*)(g_qm + (size_t)b * 4 * FF);

    float4 qm[4];
#pragma unroll
    for (int j = 0; j < 4; j++) qm[j] = qmg[j * 256 + tid];

    float4 o[4];
#pragma unroll
    for (int j = 0; j < 4; j++) o[j] = make_float4(0.f, 0.f, 0.f, 0.f);

    float m_run = -INFINITY, l_run = 0.f;  // meaningful only in warp0 lanes 0..3
    const float scale = 0.03125f;          // 1/sqrt(1024)

    for (int batch = 0; batch < NN / 4; batch++) {
        const int nbase = batch * 4;

        float4 rv[4];
#pragma unroll
        for (int r = 0; r < 4; r++) {
            int n = nbase + r;
            rv[r] = (n < NSEQ) ? x14[n * 256 + tid] : x24[(n - NSEQ) * 256 + tid];
        }

        float p[4][4];
#pragma unroll
        for (int r = 0; r < 4; r++)
#pragma unroll
            for (int j = 0; j < 4; j++) p[r][j] = dot4(rv[r], qm[j]);

#pragma unroll
        for (int r = 0; r < 4; r++)
#pragma unroll
            for (int j = 0; j < 4; j++)
#pragma unroll
                for (int off = 16; off; off >>= 1)
                    p[r][j] += __shfl_down_sync(0xffffffffu, p[r][j], off);

        if (lane == 0) {
#pragma unroll
            for (int r = 0; r < 4; r++)
#pragma unroll
                for (int j = 0; j < 4; j++) s_red[w][r * 4 + j] = p[r][j];
        }
        __syncthreads();

        if (w == 0) {
            float v = 0.f;
            if (lane < 16) {
#pragma unroll
                for (int ww = 0; ww < 8; ww++) v += s_red[ww][lane];
                v *= scale;
                s_s[nbase + (lane >> 2)][lane & 3] = v;
            }
            // lane j (<4) gathers scores of rows r=0..3 for its column j
            float t0 = __shfl_sync(0xffffffffu, v, 0 + (lane & 3));
            float t1 = __shfl_sync(0xffffffffu, v, 4 + (lane & 3));
            float t2 = __shfl_sync(0xffffffffu, v, 8 + (lane & 3));
            float t3 = __shfl_sync(0xffffffffu, v, 12 + (lane & 3));
            if (lane < 4) {
                float mn = fmaxf(fmaxf(t0, t1), fmaxf(t2, t3));
                float m_new = fmaxf(m_run, mn);
                float alpha = __expf(m_run - m_new);
                float w0 = __expf(t0 - m_new);
                float w1 = __expf(t1 - m_new);
                float w2 = __expf(t2 - m_new);
                float w3 = __expf(t3 - m_new);
                l_run = l_run * alpha + (w0 + w1 + w2 + w3);
                m_run = m_new;
                s_alpha[lane] = alpha;
                s_w[0][lane] = w0; s_w[1][lane] = w1;
                s_w[2][lane] = w2; s_w[3][lane] = w3;
            }
        }
        __syncthreads();

        {
            float a0 = s_alpha[0], a1 = s_alpha[1], a2 = s_alpha[2], a3 = s_alpha[3];
            o[0].x *= a0; o[0].y *= a0; o[0].z *= a0; o[0].w *= a0;
            o[1].x *= a1; o[1].y *= a1; o[1].z *= a1; o[1].w *= a1;
            o[2].x *= a2; o[2].y *= a2; o[2].z *= a2; o[2].w *= a2;
            o[3].x *= a3; o[3].y *= a3; o[3].z *= a3; o[3].w *= a3;
#pragma unroll
            for (int r = 0; r < 4; r++) {
                float w0 = s_w[r][0], w1 = s_w[r][1], w2 = s_w[r][2], w3 = s_w[r][3];
                o[0].x += w0 * rv[r].x; o[0].y += w0 * rv[r].y; o[0].z += w0 * rv[r].z; o[0].w += w0 * rv[r].w;
                o[1].x += w1 * rv[r].x; o[1].y += w1 * rv[r].y; o[1].z += w1 * rv[r].z; o[1].w += w1 * rv[r].w;
                o[2].x += w2 * rv[r].x; o[2].y += w2 * rv[r].y; o[2].z += w2 * rv[r].z; o[2].w += w2 * rv[r].w;
                o[3].x += w3 * rv[r].x; o[3].y += w3 * rv[r].y; o[3].z += w3 * rv[r].z; o[3].w += w3 * rv[r].w;
            }
        }
        // no barrier needed here: next iteration's __syncthreads() (before warp0
        // rewrites s_w/s_alpha) orders the reads above against those writes
    }

    if (w == 0 && lane < 4) { s_m[lane] = m_run; s_l[lane] = l_run; }
    __syncthreads();

    float mm[4], linv[4];
#pragma unroll
    for (int j = 0; j < 4; j++) { mm[j] = s_m[j]; linv[j] = 1.f / s_l[j]; }

    // out_j = 0.9 * o_j / l_j + 0.1 * qm_j ; write o1/o2 and x (concat)
#pragma unroll
    for (int j = 0; j < 4; j++) {
        float4 val;
        val.x = 0.9f * o[j].x * linv[j] + 0.1f * qm[j].x;
        val.y = 0.9f * o[j].y * linv[j] + 0.1f * qm[j].y;
        val.z = 0.9f * o[j].z * linv[j] + 0.1f * qm[j].z;
        val.w = 0.9f * o[j].w * linv[j] + 0.1f * qm[j].w;
        if (j < 2) {
            *(float4*)(out + OFF_O1 + ((size_t)b * 2 + j) * FF + 4 * tid) = val;
            *(float4*)(out + OFF_X + ((size_t)b * 2 + j) * 2048 + 4 * tid) = val;
        } else {
            *(float4*)(out + OFF_O2 + ((size_t)b * 2 + (j - 2)) * FF + 4 * tid) = val;
            *(float4*)(out + OFF_X + ((size_t)b * 2 + (j - 2)) * 2048 + 1024 + 4 * tid) = val;
        }
    }

    // A-column outputs
    if (tid < NN) {
        int n = tid;
        float s0 = s_s[n][0], s1 = s_s[n][1], s2 = s_s[n][2], s3 = s_s[n][3];
        if (n < NSEQ) {
            out[OFF_ATT1 + (size_t)b * 60 + n] = __expf(s0 - mm[0]) * linv[0];
            out[OFF_A11 + (size_t)b * 60 + n]  = __expf(s1 - mm[1]) * linv[1];
            out[OFF_A21 + (size_t)b * 60 + n]  = __expf(s3 - mm[3]) * linv[3];
        } else {
            int nn = n - NSEQ;
            out[OFF_ATT2 + (size_t)b * 60 + nn] = __expf(s2 - mm[2]) * linv[2];
            out[OFF_A12 + (size_t)b * 60 + nn]  = __expf(s1 - mm[1]) * linv[1];
            out[OFF_A22 + (size_t)b * 60 + nn]  = __expf(s3 - mm[3]) * linv[3];
        }
    }
}

// ---------------------------------------------------------------------------
extern "C" void kernel_launch(void* const* d_in, const int* in_sizes, int n_in,
                              void* d_out, int out_size)
{
    (void)in_sizes; (void)n_in; (void)out_size;
    const float* x1   = (const float*)d_in[0];
    const float* x2   = (const float*)d_in[1];
    const float* fc_w = (const float*)d_in[2];
    // d_in[3] = fc_b (unused: constant per class, doesn't affect argmax)
    const float* q_w  = (const float*)d_in[4];
    const float* q_b  = (const float*)d_in[5];
    float* out = (float*)d_out;

    dim3 g1(BB, 2);
    k_select<<<g1, 256>>>(x1, x2, fc_w, out);

    dim3 g2(16, 32);  // N/64, M/128
    k_qm<<<g2, 256>>>(q_w, q_b);

    k_attend<<<BB, 256>>>(x1, x2, out);
}

// round 2
// speedup vs baseline: 1.3747x; 1.3747x over previous
#include <cuda_runtime.h>
#include <cuda_bf16.h>
#include <math.h>
#include <stdint.h>

#define BB   1024
#define NSEQ 60
#define FF   1024
#define NN   120   // 2*NSEQ

// Output layout (flattened tuple, fp32):
// x(B,2,2048) o1(B,2,1024) o2 h1 h2 ATT1(B,60,1) ATT2 att11(B,60) att22 att12 att21
#define OFF_X    0ull
#define OFF_O1   4194304ull
#define OFF_O2   6291456ull
#define OFF_H1   8388608ull
#define OFF_H2   10485760ull
#define OFF_ATT1 12582912ull
#define OFF_ATT2 12644352ull
#define OFF_A11  12705792ull
#define OFF_A22  12767232ull
#define OFF_A12  12828672ull
#define OFF_A21  12890112ull

// Scratch
static __device__ __nv_bfloat16 g_thh[4096 * 1024];  // tanh(h) hi
static __device__ __nv_bfloat16 g_thl[4096 * 1024];  // tanh(h) lo
static __device__ __nv_bfloat16 g_qwh[1024 * 1024];  // q_w hi
static __device__ __nv_bfloat16 g_qwl[1024 * 1024];  // q_w lo
static __device__ float         g_qm[4096 * 1024];   // qm

typedef unsigned int uint32;

__device__ __forceinline__ float dot4(float4 a, float4 b) {
    return a.x * b.x + a.y * b.y + a.z * b.z + a.w * b.w;
}

__device__ __forceinline__ void split4(float4 v, uint2& uh, uint2& ul) {
    __nv_bfloat16 h0 = __float2bfloat16_rn(v.x);
    __nv_bfloat16 h1 = __float2bfloat16_rn(v.y);
    __nv_bfloat16 h2 = __float2bfloat16_rn(v.z);
    __nv_bfloat16 h3 = __float2bfloat16_rn(v.w);
    __nv_bfloat16 l0 = __float2bfloat16_rn(v.x - __bfloat162float(h0));
    __nv_bfloat16 l1 = __float2bfloat16_rn(v.y - __bfloat162float(h1));
    __nv_bfloat16 l2 = __float2bfloat16_rn(v.z - __bfloat162float(h2));
    __nv_bfloat16 l3 = __float2bfloat16_rn(v.w - __bfloat162float(h3));
    uh.x = ((uint32)__bfloat16_as_ushort(h1) << 16) | __bfloat16_as_ushort(h0);
    uh.y = ((uint32)__bfloat16_as_ushort(h3) << 16) | __bfloat16_as_ushort(h2);
    ul.x = ((uint32)__bfloat16_as_ushort(l1) << 16) | __bfloat16_as_ushort(l0);
    ul.y = ((uint32)__bfloat16_as_ushort(l3) << 16) | __bfloat16_as_ushort(l2);
}

// ---------------------------------------------------------------------------
// K0: split q_w into bf16 hi/lo
// ---------------------------------------------------------------------------
__global__ __launch_bounds__(256) void k_split_w(const float* __restrict__ qw)
{
    int idx = blockIdx.x * 256 + threadIdx.x;   // float4 index, 262144 total
    float4 v = ((const float4*)qw)[idx];
    uint2 uh, ul;
    split4(v, uh, ul);
    *(uint2*)(g_qwh + 4 * (size_t)idx) = uh;
    *(uint2*)(g_qwl + 4 * (size_t)idx) = ul;
}

// ---------------------------------------------------------------------------
// K1: logits = x @ fc_w.T ; argmax ; gather h ; write h + split(tanh(h))
// grid (B, 2), 256 threads. fc_w staged in shared (keeps regs low -> occ up).
// ---------------------------------------------------------------------------
__global__ __launch_bounds__(256) void k_select(
    const float* __restrict__ x1, const float* __restrict__ x2,
    const float* __restrict__ fc_w, float* __restrict__ out)
{
    const int b = blockIdx.x;
    const int which = blockIdx.y;
    const float* x = which ? x2 : x1;
    const float4* x4 = (const float4*)(x + (size_t)b * NSEQ * FF);

    const int tid = threadIdx.x;
    const int w = tid >> 5, lane = tid & 31;

    __shared__ float4 s_fw[512];   // fc_w[2][1024]
    __shared__ float s_log[2][64];
    __shared__ int s_idx[2];

    const float4* fw4 = (const float4*)fc_w;
    s_fw[tid] = fw4[tid];
    s_fw[tid + 256] = fw4[tid + 256];
    __syncthreads();

    for (int n = w; n < NSEQ; n += 8) {
        const float4* row = x4 + n * 256;
        float p0 = 0.f, p1 = 0.f;
#pragma unroll
        for (int i = 0; i < 8; i++) {
            float4 v = row[lane + 32 * i];
            p0 += dot4(v, s_fw[lane + 32 * i]);
            p1 += dot4(v, s_fw[256 + lane + 32 * i]);
        }
#pragma unroll
        for (int off = 16; off; off >>= 1) {
            p0 += __shfl_down_sync(0xffffffffu, p0, off);
            p1 += __shfl_down_sync(0xffffffffu, p1, off);
        }
        if (lane == 0) { s_log[0][n] = p0; s_log[1][n] = p1; }
    }
    __syncthreads();

    if (tid < 2) {
        float best = s_log[tid][0];
        int bi = 0;
        for (int n = 1; n < NSEQ; n++) {
            float v = s_log[tid][n];
            if (v > best) { best = v; bi = n; }
        }
        s_idx[tid] = bi;
    }
    __syncthreads();

    const int i0 = s_idx[0], i1 = s_idx[1];
    float4* h4 = (float4*)(out + (which ? OFF_H2 : OFF_H1) + (size_t)b * 2 * FF);
    const size_t row0 = ((size_t)b * 4 + which * 2) * FF;

    float4 v = x4[i0 * 256 + tid];
    h4[tid] = v;
    float4 t0 = make_float4(tanhf(v.x), tanhf(v.y), tanhf(v.z), tanhf(v.w));
    uint2 uh, ul;
    split4(t0, uh, ul);
    *(uint2*)(g_thh + row0 + 4 * tid) = uh;
    *(uint2*)(g_thl + row0 + 4 * tid) = ul;

    v = x4[i1 * 256 + tid];
    h4[256 + tid] = v;
    float4 t1 = make_float4(tanhf(v.x), tanhf(v.y), tanhf(v.z), tanhf(v.w));
    split4(t1, uh, ul);
    *(uint2*)(g_thh + row0 + FF + 4 * tid) = uh;
    *(uint2*)(g_thl + row0 + FF + 4 * tid) = ul;
}

// ---------------------------------------------------------------------------
// K2: qm = tanh(h) @ q_w.T + q_b via 3xBF16 tensor-core GEMM
// M=4096 N=1024 K=1024. BM=BN=128, BK=16, 256 thr (8 warps, 4m x 2n),
// cp.async double-buffered, ldmatrix fragments, mma.sync m16n8k16 bf16.
// Per k16 per warp: acc += Ahi*Bhi + Ahi*Blo + Alo*Bhi
// ---------------------------------------------------------------------------
#define QM_STAGE_BYTES 24576            // 4 tiles x 128 rows x 48B
#define QM_ROWB 48                      // padded row stride (16 bf16 = 32B + 16B pad)
#define QM_AH 0
#define QM_AL 6144
#define QM_BH 12288
#define QM_BL 18432

__device__ __forceinline__ void ldsm4(uint32* r, uint32 addr) {
    asm volatile("ldmatrix.sync.aligned.m8n8.x4.shared.b16 {%0,%1,%2,%3}, [%4];"
                 : "=r"(r[0]), "=r"(r[1]), "=r"(r[2]), "=r"(r[3]) : "r"(addr));
}
__device__ __forceinline__ void mma_bf16(float* c, const uint32* a, uint32 b0, uint32 b1) {
    asm volatile(
        "mma.sync.aligned.m16n8k16.row.col.f32.bf16.bf16.f32 "
        "{%0,%1,%2,%3}, {%4,%5,%6,%7}, {%8,%9}, {%0,%1,%2,%3};"
        : "+f"(c[0]), "+f"(c[1]), "+f"(c[2]), "+f"(c[3])
        : "r"(a[0]), "r"(a[1]), "r"(a[2]), "r"(a[3]), "r"(b0), "r"(b1));
}
__device__ __forceinline__ void cpa16(uint32 dst, const void* src) {
    asm volatile("cp.async.cg.shared.global [%0], [%1], 16;" :: "r"(dst), "l"(src));
}

__global__ __launch_bounds__(256, 1) void k_qm_mma(const float* __restrict__ qb)
{
    __shared__ __align__(128) unsigned char smem[2 * QM_STAGE_BYTES];

    const int tid = threadIdx.x;
    const int lane = tid & 31;
    const int wid = tid >> 5;
    const int warp_m = wid >> 1;        // 0..3
    const int warp_n = wid & 1;         // 0..1
    const int m0 = blockIdx.y * 128;
    const int n0 = blockIdx.x * 128;

    const uint32 sbase = (uint32)__cvta_generic_to_shared(smem);

    // load indices
    const int lrow = tid >> 1;          // 0..127
    const int lch  = tid & 1;           // 16B chunk within row
    const uint32 ldst = lrow * QM_ROWB + lch * 16;

    // ldmatrix lane addresses (byte offsets within a tile)
    const int ag = lane >> 3;
    const uint32 a_off = (warp_m * 32 + (lane & 7) + (ag & 1) * 8) * QM_ROWB + (ag >> 1) * 16;
    const uint32 b_off = (warp_n * 64 + (lane & 7) + ((lane >> 4) & 1) * 8) * QM_ROWB
                         + ((lane >> 3) & 1) * 16;

    float c[2][8][4];
#pragma unroll
    for (int mt = 0; mt < 2; mt++)
#pragma unroll
        for (int nt = 0; nt < 8; nt++)
#pragma unroll
            for (int i = 0; i < 4; i++) c[mt][nt][i] = 0.f;

    // prologue: stage 0
    {
        const size_t ka = (size_t)(m0 + lrow) * 1024 + lch * 8;
        const size_t kb = (size_t)(n0 + lrow) * 1024 + lch * 8;
        cpa16(sbase + QM_AH + ldst, g_thh + ka);
        cpa16(sbase + QM_AL + ldst, g_thl + ka);
        cpa16(sbase + QM_BH + ldst, g_qwh + kb);
        cpa16(sbase + QM_BL + ldst, g_qwl + kb);
        asm volatile("cp.async.commit_group;");
    }

    for (int it = 0; it < 64; it++) {
        const uint32 cur = (it & 1) * QM_STAGE_BYTES;
        asm volatile("cp.async.wait_group 0;");
        __syncthreads();

        if (it < 63) {
            const uint32 nxt = ((it + 1) & 1) * QM_STAGE_BYTES;
            const size_t ka = (size_t)(m0 + lrow) * 1024 + (it + 1) * 16 + lch * 8;
            const size_t kb = (size_t)(n0 + lrow) * 1024 + (it + 1) * 16 + lch * 8;
            cpa16(sbase + nxt + QM_AH + ldst, g_thh + ka);
            cpa16(sbase + nxt + QM_AL + ldst, g_thl + ka);
            cpa16(sbase + nxt + QM_BH + ldst, g_qwh + kb);
            cpa16(sbase + nxt + QM_BL + ldst, g_qwl + kb);
            asm volatile("cp.async.commit_group;");
        }

        uint32 ah[2][4], al[2][4];
#pragma unroll
        for (int mt = 0; mt < 2; mt++) {
            ldsm4(ah[mt], sbase + cur + QM_AH + a_off + mt * 16 * QM_ROWB);
            ldsm4(al[mt], sbase + cur + QM_AL + a_off + mt * 16 * QM_ROWB);
        }
#pragma unroll
        for (int p = 0; p < 4; p++) {
            uint32 bh[4], bl[4];
            ldsm4(bh, sbase + cur + QM_BH + b_off + p * 16 * QM_ROWB);
            ldsm4(bl, sbase + cur + QM_BL + b_off + p * 16 * QM_ROWB);
#pragma unroll
            for (int mt = 0; mt < 2; mt++) {
                mma_bf16(c[mt][2 * p],     ah[mt], bh[0], bh[1]);
                mma_bf16(c[mt][2 * p],     ah[mt], bl[0], bl[1]);
                mma_bf16(c[mt][2 * p],     al[mt], bh[0], bh[1]);
                mma_bf16(c[mt][2 * p + 1], ah[mt], bh[2], bh[3]);
                mma_bf16(c[mt][2 * p + 1], ah[mt], bl[2], bl[3]);
                mma_bf16(c[mt][2 * p + 1], al[mt], bh[2], bh[3]);
            }
        }
    }

    // epilogue: add bias, store
#pragma unroll
    for (int mt = 0; mt < 2; mt++) {
        const int mg = m0 + warp_m * 32 + mt * 16 + (lane >> 2);
#pragma unroll
        for (int nt = 0; nt < 8; nt++) {
            const int ng = n0 + warp_n * 64 + nt * 8 + 2 * (lane & 3);
            const float b0 = __ldg(qb + ng), b1 = __ldg(qb + ng + 1);
            *(float2*)(g_qm + (size_t)mg * 1024 + ng) =
                make_float2(c[mt][nt][0] + b0, c[mt][nt][1] + b1);
            *(float2*)(g_qm + (size_t)(mg + 8) * 1024 + ng) =
                make_float2(c[mt][nt][2] + b0, c[mt][nt][3] + b1);
        }
    }
}

// ---------------------------------------------------------------------------
// K3: fused attention with online softmax — single pass over L = [x1;x2]
// ---------------------------------------------------------------------------
__global__ __launch_bounds__(256) void k_attend(
    const float* __restrict__ x1, const float* __restrict__ x2,
    float* __restrict__ out)
{
    const int b = blockIdx.x;
    const int tid = threadIdx.x;
    const int w = tid >> 5, lane = tid & 31;

    __shared__ float s_s[NN][4];
    __shared__ float s_w[4][4];
    __shared__ float s_alpha[4];
    __shared__ float s_red[8][16];
    __shared__ float s_m[4], s_l[4];

    const float4* x14 = (const float4*)(x1 + (size_t)b * NSEQ * FF);
    const float4* x24 = (const float4*)(x2 + (size_t)b * NSEQ * FF);
    const float4* qmg = (const float4*)(g_qm + (size_t)b * 4 * FF);

    float4 qm[4];
#pragma unroll
    for (int j = 0; j < 4; j++) qm[j] = qmg[j * 256 + tid];

    float4 o[4];
#pragma unroll
    for (int j = 0; j < 4; j++) o[j] = make_float4(0.f, 0.f, 0.f, 0.f);

    float m_run = -INFINITY, l_run = 0.f;
    const float scale = 0.03125f;

    for (int batch = 0; batch < NN / 4; batch++) {
        const int nbase = batch * 4;

        float4 rv[4];
#pragma unroll
        for (int r = 0; r < 4; r++) {
            int n = nbase + r;
            rv[r] = (n < NSEQ) ? x14[n * 256 + tid] : x24[(n - NSEQ) * 256 + tid];
        }

        float p[4][4];
#pragma unroll
        for (int r = 0; r < 4; r++)
#pragma unroll
            for (int j = 0; j < 4; j++) p[r][j] = dot4(rv[r], qm[j]);

#pragma unroll
        for (int r = 0; r < 4; r++)
#pragma unroll
            for (int j = 0; j < 4; j++)
#pragma unroll
                for (int off = 16; off; off >>= 1)
                    p[r][j] += __shfl_down_sync(0xffffffffu, p[r][j], off);

        if (lane == 0) {
#pragma unroll
            for (int r = 0; r < 4; r++)
#pragma unroll
                for (int j = 0; j < 4; j++) s_red[w][r * 4 + j] = p[r][j];
        }
        __syncthreads();

        if (w == 0) {
            float v = 0.f;
            if (lane < 16) {
#pragma unroll
                for (int ww = 0; ww < 8; ww++) v += s_red[ww][lane];
                v *= scale;
                s_s[nbase + (lane >> 2)][lane & 3] = v;
            }
            float t0 = __shfl_sync(0xffffffffu, v, 0 + (lane & 3));
            float t1 = __shfl_sync(0xffffffffu, v, 4 + (lane & 3));
            float t2 = __shfl_sync(0xffffffffu, v, 8 + (lane & 3));
            float t3 = __shfl_sync(0xffffffffu, v, 12 + (lane & 3));
            if (lane < 4) {
                float mn = fmaxf(fmaxf(t0, t1), fmaxf(t2, t3));
                float m_new = fmaxf(m_run, mn);
                float alpha = __expf(m_run - m_new);
                float w0 = __expf(t0 - m_new);
                float w1 = __expf(t1 - m_new);
                float w2 = __expf(t2 - m_new);
                float w3 = __expf(t3 - m_new);
                l_run = l_run * alpha + (w0 + w1 + w2 + w3);
                m_run = m_new;
                s_alpha[lane] = alpha;
                s_w[0][lane] = w0; s_w[1][lane] = w1;
                s_w[2][lane] = w2; s_w[3][lane] = w3;
            }
        }
        __syncthreads();

        {
            float a0 = s_alpha[0], a1 = s_alpha[1], a2 = s_alpha[2], a3 = s_alpha[3];
            o[0].x *= a0; o[0].y *= a0; o[0].z *= a0; o[0].w *= a0;
            o[1].x *= a1; o[1].y *= a1; o[1].z *= a1; o[1].w *= a1;
            o[2].x *= a2; o[2].y *= a2; o[2].z *= a2; o[2].w *= a2;
            o[3].x *= a3; o[3].y *= a3; o[3].z *= a3; o[3].w *= a3;
#pragma unroll
            for (int r = 0; r < 4; r++) {
                float w0 = s_w[r][0], w1 = s_w[r][1], w2 = s_w[r][2], w3 = s_w[r][3];
                o[0].x += w0 * rv[r].x; o[0].y += w0 * rv[r].y; o[0].z += w0 * rv[r].z; o[0].w += w0 * rv[r].w;
                o[1].x += w1 * rv[r].x; o[1].y += w1 * rv[r].y; o[1].z += w1 * rv[r].z; o[1].w += w1 * rv[r].w;
                o[2].x += w2 * rv[r].x; o[2].y += w2 * rv[r].y; o[2].z += w2 * rv[r].z; o[2].w += w2 * rv[r].w;
                o[3].x += w3 * rv[r].x; o[3].y += w3 * rv[r].y; o[3].z += w3 * rv[r].z; o[3].w += w3 * rv[r].w;
            }
        }
    }

    if (w == 0 && lane < 4) { s_m[lane] = m_run; s_l[lane] = l_run; }
    __syncthreads();

    float mm[4], linv[4];
#pragma unroll
    for (int j = 0; j < 4; j++) { mm[j] = s_m[j]; linv[j] = 1.f / s_l[j]; }

#pragma unroll
    for (int j = 0; j < 4; j++) {
        float4 val;
        val.x = 0.9f * o[j].x * linv[j] + 0.1f * qm[j].x;
        val.y = 0.9f * o[j].y * linv[j] + 0.1f * qm[j].y;
        val.z = 0.9f * o[j].z * linv[j] + 0.1f * qm[j].z;
        val.w = 0.9f * o[j].w * linv[j] + 0.1f * qm[j].w;
        if (j < 2) {
            *(float4*)(out + OFF_O1 + ((size_t)b * 2 + j) * FF + 4 * tid) = val;
            *(float4*)(out + OFF_X + ((size_t)b * 2 + j) * 2048 + 4 * tid) = val;
        } else {
            *(float4*)(out + OFF_O2 + ((size_t)b * 2 + (j - 2)) * FF + 4 * tid) = val;
            *(float4*)(out + OFF_X + ((size_t)b * 2 + (j - 2)) * 2048 + 1024 + 4 * tid) = val;
        }
    }

    if (tid < NN) {
        int n = tid;
        float s0 = s_s[n][0], s1 = s_s[n][1], s2 = s_s[n][2], s3 = s_s[n][3];
        if (n < NSEQ) {
            out[OFF_ATT1 + (size_t)b * 60 + n] = __expf(s0 - mm[0]) * linv[0];
            out[OFF_A11 + (size_t)b * 60 + n]  = __expf(s1 - mm[1]) * linv[1];
            out[OFF_A21 + (size_t)b * 60 + n]  = __expf(s3 - mm[3]) * linv[3];
        } else {
            int nn = n - NSEQ;
            out[OFF_ATT2 + (size_t)b * 60 + nn] = __expf(s2 - mm[2]) * linv[2];
            out[OFF_A12 + (size_t)b * 60 + nn]  = __expf(s1 - mm[1]) * linv[1];
            out[OFF_A22 + (size_t)b * 60 + nn]  = __expf(s3 - mm[3]) * linv[3];
        }
    }
}

// ---------------------------------------------------------------------------
extern "C" void kernel_launch(void* const* d_in, const int* in_sizes, int n_in,
                              void* d_out, int out_size)
{
    (void)in_sizes; (void)n_in; (void)out_size;
    const float* x1   = (const float*)d_in[0];
    const float* x2   = (const float*)d_in[1];
    const float* fc_w = (const float*)d_in[2];
    // d_in[3] = fc_b (constant per class: doesn't change argmax over n)
    const float* q_w  = (const float*)d_in[4];
    const float* q_b  = (const float*)d_in[5];
    float* out = (float*)d_out;

    k_split_w<<<1024, 256>>>(q_w);

    dim3 g1(BB, 2);
    k_select<<<g1, 256>>>(x1, x2, fc_w, out);

    dim3 g2(8, 32);   // N/128, M/128
    k_qm_mma<<<g2, 256>>>(q_b);

    k_attend<<<BB, 256>>>(x1, x2, out);
}

// round 3
// speedup vs baseline: 1.5195x; 1.1053x over previous
#include <cuda_runtime.h>
#include <cuda_bf16.h>
#include <math.h>
#include <stdint.h>

#define BB   1024
#define NSEQ 60
#define FF   1024
#define NN   120   // 2*NSEQ

// Output layout (flattened tuple, fp32):
// x(B,2,2048) o1(B,2,1024) o2 h1 h2 ATT1(B,60,1) ATT2 att11(B,60) att22 att12 att21
#define OFF_X    0ull
#define OFF_O1   4194304ull
#define OFF_O2   6291456ull
#define OFF_H1   8388608ull
#define OFF_H2   10485760ull
#define OFF_ATT1 12582912ull
#define OFF_ATT2 12644352ull
#define OFF_A11  12705792ull
#define OFF_A22  12767232ull
#define OFF_A12  12828672ull
#define OFF_A21  12890112ull

// Scratch
static __device__ __nv_bfloat16 g_thh[4096 * 1024];  // tanh(h) hi
static __device__ __nv_bfloat16 g_thl[4096 * 1024];  // tanh(h) lo
static __device__ __nv_bfloat16 g_qwh[1024 * 1024];  // q_w hi
static __device__ __nv_bfloat16 g_qwl[1024 * 1024];  // q_w lo
static __device__ float         g_qm[4096 * 1024];   // qm

typedef unsigned int uint32;
#define FULLW 0xffffffffu

__device__ __forceinline__ float dot4(float4 a, float4 b) {
    return a.x * b.x + a.y * b.y + a.z * b.z + a.w * b.w;
}

__device__ __forceinline__ void split4(float4 v, uint2& uh, uint2& ul) {
    __nv_bfloat16 h0 = __float2bfloat16_rn(v.x);
    __nv_bfloat16 h1 = __float2bfloat16_rn(v.y);
    __nv_bfloat16 h2 = __float2bfloat16_rn(v.z);
    __nv_bfloat16 h3 = __float2bfloat16_rn(v.w);
    __nv_bfloat16 l0 = __float2bfloat16_rn(v.x - __bfloat162float(h0));
    __nv_bfloat16 l1 = __float2bfloat16_rn(v.y - __bfloat162float(h1));
    __nv_bfloat16 l2 = __float2bfloat16_rn(v.z - __bfloat162float(h2));
    __nv_bfloat16 l3 = __float2bfloat16_rn(v.w - __bfloat162float(h3));
    uh.x = ((uint32)__bfloat16_as_ushort(h1) << 16) | __bfloat16_as_ushort(h0);
    uh.y = ((uint32)__bfloat16_as_ushort(h3) << 16) | __bfloat16_as_ushort(h2);
    ul.x = ((uint32)__bfloat16_as_ushort(l1) << 16) | __bfloat16_as_ushort(l0);
    ul.y = ((uint32)__bfloat16_as_ushort(l3) << 16) | __bfloat16_as_ushort(l2);
}

// ---------------------------------------------------------------------------
// K0: split q_w into bf16 hi/lo
// ---------------------------------------------------------------------------
__global__ __launch_bounds__(256) void k_split_w(const float* __restrict__ qw)
{
    int idx = blockIdx.x * 256 + threadIdx.x;
    float4 v = ((const float4*)qw)[idx];
    uint2 uh, ul;
    split4(v, uh, ul);
    *(uint2*)(g_qwh + 4 * (size_t)idx) = uh;
    *(uint2*)(g_qwl + 4 * (size_t)idx) = ul;
}

// ---------------------------------------------------------------------------
// K1: logits = x @ fc_w.T ; argmax ; gather h ; write h + split(tanh(h))
// ---------------------------------------------------------------------------
__global__ __launch_bounds__(256) void k_select(
    const float* __restrict__ x1, const float* __restrict__ x2,
    const float* __restrict__ fc_w, float* __restrict__ out)
{
    const int b = blockIdx.x;
    const int which = blockIdx.y;
    const float* x = which ? x2 : x1;
    const float4* x4 = (const float4*)(x + (size_t)b * NSEQ * FF);

    const int tid = threadIdx.x;
    const int w = tid >> 5, lane = tid & 31;

    __shared__ float4 s_fw[512];
    __shared__ float s_log[2][64];
    __shared__ int s_idx[2];

    const float4* fw4 = (const float4*)fc_w;
    s_fw[tid] = fw4[tid];
    s_fw[tid + 256] = fw4[tid + 256];
    __syncthreads();

    for (int n = w; n < NSEQ; n += 8) {
        const float4* row = x4 + n * 256;
        float p0 = 0.f, p1 = 0.f;
#pragma unroll
        for (int i = 0; i < 8; i++) {
            float4 v = row[lane + 32 * i];
            p0 += dot4(v, s_fw[lane + 32 * i]);
            p1 += dot4(v, s_fw[256 + lane + 32 * i]);
        }
#pragma unroll
        for (int off = 16; off; off >>= 1) {
            p0 += __shfl_down_sync(FULLW, p0, off);
            p1 += __shfl_down_sync(FULLW, p1, off);
        }
        if (lane == 0) { s_log[0][n] = p0; s_log[1][n] = p1; }
    }
    __syncthreads();

    if (tid < 2) {
        float best = s_log[tid][0];
        int bi = 0;
        for (int n = 1; n < NSEQ; n++) {
            float v = s_log[tid][n];
            if (v > best) { best = v; bi = n; }
        }
        s_idx[tid] = bi;
    }
    __syncthreads();

    const int i0 = s_idx[0], i1 = s_idx[1];
    float4* h4 = (float4*)(out + (which ? OFF_H2 : OFF_H1) + (size_t)b * 2 * FF);
    const size_t row0 = ((size_t)b * 4 + which * 2) * FF;

    float4 v = x4[i0 * 256 + tid];
    h4[tid] = v;
    float4 t0 = make_float4(tanhf(v.x), tanhf(v.y), tanhf(v.z), tanhf(v.w));
    uint2 uh, ul;
    split4(t0, uh, ul);
    *(uint2*)(g_thh + row0 + 4 * tid) = uh;
    *(uint2*)(g_thl + row0 + 4 * tid) = ul;

    v = x4[i1 * 256 + tid];
    h4[256 + tid] = v;
    float4 t1 = make_float4(tanhf(v.x), tanhf(v.y), tanhf(v.z), tanhf(v.w));
    split4(t1, uh, ul);
    *(uint2*)(g_thh + row0 + FF + 4 * tid) = uh;
    *(uint2*)(g_thl + row0 + FF + 4 * tid) = ul;
}

// ---------------------------------------------------------------------------
// K2: qm = tanh(h) @ q_w.T + q_b via 3xBF16 tensor-core GEMM
// 3-stage cp.async pipeline (dynamic smem), wait_group 1.
// ---------------------------------------------------------------------------
#define QM_STAGE_BYTES 24576
#define QM_ROWB 48
#define QM_AH 0
#define QM_AL 6144
#define QM_BH 12288
#define QM_BL 18432
#define QM_SMEM (3 * QM_STAGE_BYTES)

__device__ __forceinline__ void ldsm4(uint32* r, uint32 addr) {
    asm volatile("ldmatrix.sync.aligned.m8n8.x4.shared.b16 {%0,%1,%2,%3}, [%4];"
                 : "=r"(r[0]), "=r"(r[1]), "=r"(r[2]), "=r"(r[3]) : "r"(addr));
}
__device__ __forceinline__ void mma_bf16(float* c, const uint32* a, uint32 b0, uint32 b1) {
    asm volatile(
        "mma.sync.aligned.m16n8k16.row.col.f32.bf16.bf16.f32 "
        "{%0,%1,%2,%3}, {%4,%5,%6,%7}, {%8,%9}, {%0,%1,%2,%3};"
        : "+f"(c[0]), "+f"(c[1]), "+f"(c[2]), "+f"(c[3])
        : "r"(a[0]), "r"(a[1]), "r"(a[2]), "r"(a[3]), "r"(b0), "r"(b1));
}
__device__ __forceinline__ void cpa16(uint32 dst, const void* src) {
    asm volatile("cp.async.cg.shared.global [%0], [%1], 16;" :: "r"(dst), "l"(src));
}

__global__ __launch_bounds__(256, 1) void k_qm_mma(const float* __restrict__ qb)
{
    extern __shared__ __align__(128) unsigned char smem[];

    const int tid = threadIdx.x;
    const int lane = tid & 31;
    const int wid = tid >> 5;
    const int warp_m = wid >> 1;
    const int warp_n = wid & 1;
    const int m0 = blockIdx.y * 128;
    const int n0 = blockIdx.x * 128;

    const uint32 sbase = (uint32)__cvta_generic_to_shared(smem);

    const int lrow = tid >> 1;
    const int lch  = tid & 1;
    const uint32 ldst = lrow * QM_ROWB + lch * 16;

    const int ag = lane >> 3;
    const uint32 a_off = (warp_m * 32 + (lane & 7) + (ag & 1) * 8) * QM_ROWB + (ag >> 1) * 16;
    const uint32 b_off = (warp_n * 64 + (lane & 7) + ((lane >> 4) & 1) * 8) * QM_ROWB
                         + ((lane >> 3) & 1) * 16;

    float c[2][8][4];
#pragma unroll
    for (int mt = 0; mt < 2; mt++)
#pragma unroll
        for (int nt = 0; nt < 8; nt++)
#pragma unroll
            for (int i = 0; i < 4; i++) c[mt][nt][i] = 0.f;

    // prologue: stages 0, 1
#pragma unroll
    for (int s = 0; s < 2; s++) {
        const uint32 st = s * QM_STAGE_BYTES;
        const size_t ka = (size_t)(m0 + lrow) * 1024 + s * 16 + lch * 8;
        const size_t kb = (size_t)(n0 + lrow) * 1024 + s * 16 + lch * 8;
        cpa16(sbase + st + QM_AH + ldst, g_thh + ka);
        cpa16(sbase + st + QM_AL + ldst, g_thl + ka);
        cpa16(sbase + st + QM_BH + ldst, g_qwh + kb);
        cpa16(sbase + st + QM_BL + ldst, g_qwl + kb);
        asm volatile("cp.async.commit_group;");
    }

    int cur_s = 0, nxt_s = 2;
    for (int it = 0; it < 64; it++) {
        const uint32 cur = cur_s * QM_STAGE_BYTES;
        asm volatile("cp.async.wait_group 1;");
        __syncthreads();

        if (it < 62) {
            const uint32 nxt = nxt_s * QM_STAGE_BYTES;
            const size_t ka = (size_t)(m0 + lrow) * 1024 + (it + 2) * 16 + lch * 8;
            const size_t kb = (size_t)(n0 + lrow) * 1024 + (it + 2) * 16 + lch * 8;
            cpa16(sbase + nxt + QM_AH + ldst, g_thh + ka);
            cpa16(sbase + nxt + QM_AL + ldst, g_thl + ka);
            cpa16(sbase + nxt + QM_BH + ldst, g_qwh + kb);
            cpa16(sbase + nxt + QM_BL + ldst, g_qwl + kb);
            asm volatile("cp.async.commit_group;");
        } else {
            asm volatile("cp.async.commit_group;");  // empty group keeps accounting uniform
        }

        uint32 ah[2][4], al[2][4];
#pragma unroll
        for (int mt = 0; mt < 2; mt++) {
            ldsm4(ah[mt], sbase + cur + QM_AH + a_off + mt * 16 * QM_ROWB);
            ldsm4(al[mt], sbase + cur + QM_AL + a_off + mt * 16 * QM_ROWB);
        }
#pragma unroll
        for (int p = 0; p < 4; p++) {
            uint32 bh[4], bl[4];
            ldsm4(bh, sbase + cur + QM_BH + b_off + p * 16 * QM_ROWB);
            ldsm4(bl, sbase + cur + QM_BL + b_off + p * 16 * QM_ROWB);
#pragma unroll
            for (int mt = 0; mt < 2; mt++) {
                mma_bf16(c[mt][2 * p],     ah[mt], bh[0], bh[1]);
                mma_bf16(c[mt][2 * p],     ah[mt], bl[0], bl[1]);
                mma_bf16(c[mt][2 * p],     al[mt], bh[0], bh[1]);
                mma_bf16(c[mt][2 * p + 1], ah[mt], bh[2], bh[3]);
                mma_bf16(c[mt][2 * p + 1], ah[mt], bl[2], bl[3]);
                mma_bf16(c[mt][2 * p + 1], al[mt], bh[2], bh[3]);
            }
        }
        cur_s = (cur_s == 2) ? 0 : cur_s + 1;
        nxt_s = (nxt_s == 2) ? 0 : nxt_s + 1;
    }

#pragma unroll
    for (int mt = 0; mt < 2; mt++) {
        const int mg = m0 + warp_m * 32 + mt * 16 + (lane >> 2);
#pragma unroll
        for (int nt = 0; nt < 8; nt++) {
            const int ng = n0 + warp_n * 64 + nt * 8 + 2 * (lane & 3);
            const float b0 = __ldg(qb + ng), b1 = __ldg(qb + ng + 1);
            *(float2*)(g_qm + (size_t)mg * 1024 + ng) =
                make_float2(c[mt][nt][0] + b0, c[mt][nt][1] + b1);
            *(float2*)(g_qm + (size_t)(mg + 8) * 1024 + ng) =
                make_float2(c[mt][nt][2] + b0, c[mt][nt][3] + b1);
        }
    }
}

// ---------------------------------------------------------------------------
// K3: fused attention, online softmax — 1 barrier/iter, prefetch, 31-shuffle
// multi-value reduction, redundant per-warp softmax state.
// ---------------------------------------------------------------------------
__device__ __forceinline__ void att_step(
    int nbase, const float4 rv[4], const float4 qm[4],
    float4 o[4], float& m_run, float& l_run,
    float (*s_red)[16], float (*s_s)[4], int w, int lane, float scale)
{
    float p[16];
#pragma unroll
    for (int r = 0; r < 4; r++)
#pragma unroll
        for (int j = 0; j < 4; j++) p[r * 4 + j] = dot4(rv[r], qm[j]);

    // multi-value butterfly: 31 shuffles; value v ends on lanes 2v, 2v+1
#pragma unroll
    for (int v = 0; v < 16; v++) p[v] += __shfl_xor_sync(FULLW, p[v], 16);
    float q8[8];
#pragma unroll
    for (int v = 0; v < 8; v++) q8[v] = (lane & 16) ? p[v + 8] : p[v];
#pragma unroll
    for (int v = 0; v < 8; v++) q8[v] += __shfl_xor_sync(FULLW, q8[v], 8);
    float q4[4];
#pragma unroll
    for (int v = 0; v < 4; v++) q4[v] = (lane & 8) ? q8[v + 4] : q8[v];
#pragma unroll
    for (int v = 0; v < 4; v++) q4[v] += __shfl_xor_sync(FULLW, q4[v], 4);
    float q2[2];
#pragma unroll
    for (int v = 0; v < 2; v++) q2[v] = (lane & 4) ? q4[v + 2] : q4[v];
#pragma unroll
    for (int v = 0; v < 2; v++) q2[v] += __shfl_xor_sync(FULLW, q2[v], 2);
    float q1 = (lane & 2) ? q2[1] : q2[0];
    q1 += __shfl_xor_sync(FULLW, q1, 1);

    if (!(lane & 1)) s_red[w][lane >> 1] = q1;
    __syncthreads();

    // every warp redundantly reduces across warps + computes softmax update
    float v16 = 0.f;
    if (lane < 16) {
#pragma unroll
        for (int ww = 0; ww < 8; ww++) v16 += s_red[ww][lane];
        v16 *= scale;
    }
    if (w == 0 && lane < 16) s_s[nbase + (lane >> 2)][lane & 3] = v16;

    const int j = lane & 3;
    float t0 = __shfl_sync(FULLW, v16, j);
    float t1 = __shfl_sync(FULLW, v16, 4 + j);
    float t2 = __shfl_sync(FULLW, v16, 8 + j);
    float t3 = __shfl_sync(FULLW, v16, 12 + j);

    float mn = fmaxf(fmaxf(t0, t1), fmaxf(t2, t3));
    float m_new = fmaxf(m_run, mn);
    float alpha = __expf(m_run - m_new);
    float w0 = __expf(t0 - m_new);
    float w1 = __expf(t1 - m_new);
    float w2 = __expf(t2 - m_new);
    float w3 = __expf(t3 - m_new);
    l_run = l_run * alpha + (w0 + w1 + w2 + w3);
    m_run = m_new;

    // rescale + accumulate (broadcast from lanes 0..3 which hold cols 0..3)
#pragma unroll
    for (int jj = 0; jj < 4; jj++) {
        float a = __shfl_sync(FULLW, alpha, jj);
        o[jj].x *= a; o[jj].y *= a; o[jj].z *= a; o[jj].w *= a;
    }
#pragma unroll
    for (int r = 0; r < 4; r++) {
        float wr = (r == 0) ? w0 : (r == 1) ? w1 : (r == 2) ? w2 : w3;
        float wa = __shfl_sync(FULLW, wr, 0);
        float wb = __shfl_sync(FULLW, wr, 1);
        float wc = __shfl_sync(FULLW, wr, 2);
        float wd = __shfl_sync(FULLW, wr, 3);
        o[0].x += wa * rv[r].x; o[0].y += wa * rv[r].y; o[0].z += wa * rv[r].z; o[0].w += wa * rv[r].w;
        o[1].x += wb * rv[r].x; o[1].y += wb * rv[r].y; o[1].z += wb * rv[r].z; o[1].w += wb * rv[r].w;
        o[2].x += wc * rv[r].x; o[2].y += wc * rv[r].y; o[2].z += wc * rv[r].z; o[2].w += wc * rv[r].w;
        o[3].x += wd * rv[r].x; o[3].y += wd * rv[r].y; o[3].z += wd * rv[r].z; o[3].w += wd * rv[r].w;
    }
}

__global__ __launch_bounds__(256) void k_attend(
    const float* __restrict__ x1, const float* __restrict__ x2,
    float* __restrict__ out)
{
    const int b = blockIdx.x;
    const int tid = threadIdx.x;
    const int w = tid >> 5, lane = tid & 31;

    __shared__ float s_s[NN][4];
    __shared__ float s_red[2][8][16];

    const float4* x14 = (const float4*)(x1 + (size_t)b * NSEQ * FF);
    const float4* x24 = (const float4*)(x2 + (size_t)b * NSEQ * FF);
    const float4* qmg = (const float4*)(g_qm + (size_t)b * 4 * FF);

    float4 qm[4];
#pragma unroll
    for (int j = 0; j < 4; j++) qm[j] = qmg[j * 256 + tid];

    float4 o[4];
#pragma unroll
    for (int j = 0; j < 4; j++) o[j] = make_float4(0.f, 0.f, 0.f, 0.f);

    float m_run = -INFINITY, l_run = 0.f;  // per-lane, column lane&3
    const float scale = 0.03125f;

    float4 rva[4], rvb[4];
#pragma unroll
    for (int r = 0; r < 4; r++) rva[r] = x14[r * 256 + tid];

    for (int bt = 0; bt < 30; bt += 2) {
        // prefetch batch bt+1
        {
            const int nb = (bt + 1) * 4;
            const float4* pb = (bt + 1 < 15) ? (x14 + nb * 256) : (x24 + (nb - NSEQ) * 256);
#pragma unroll
            for (int r = 0; r < 4; r++) rvb[r] = pb[r * 256 + tid];
        }
        att_step(bt * 4, rva, qm, o, m_run, l_run, s_red[0], s_s, w, lane, scale);
        // prefetch batch bt+2
        if (bt + 2 < 30) {
            const int nb = (bt + 2) * 4;
            const float4* pb = (bt + 2 < 15) ? (x14 + nb * 256) : (x24 + (nb - NSEQ) * 256);
#pragma unroll
            for (int r = 0; r < 4; r++) rva[r] = pb[r * 256 + tid];
        }
        att_step((bt + 1) * 4, rvb, qm, o, m_run, l_run, s_red[1], s_s, w, lane, scale);
    }
    __syncthreads();

    float mm[4], linv[4];
#pragma unroll
    for (int j = 0; j < 4; j++) {
        mm[j] = __shfl_sync(FULLW, m_run, j);
        linv[j] = 1.f / __shfl_sync(FULLW, l_run, j);
    }

#pragma unroll
    for (int j = 0; j < 4; j++) {
        float4 val;
        val.x = 0.9f * o[j].x * linv[j] + 0.1f * qm[j].x;
        val.y = 0.9f * o[j].y * linv[j] + 0.1f * qm[j].y;
        val.z = 0.9f * o[j].z * linv[j] + 0.1f * qm[j].z;
        val.w = 0.9f * o[j].w * linv[j] + 0.1f * qm[j].w;
        if (j < 2) {
            *(float4*)(out + OFF_O1 + ((size_t)b * 2 + j) * FF + 4 * tid) = val;
            *(float4*)(out + OFF_X + ((size_t)b * 2 + j) * 2048 + 4 * tid) = val;
        } else {
            *(float4*)(out + OFF_O2 + ((size_t)b * 2 + (j - 2)) * FF + 4 * tid) = val;
            *(float4*)(out + OFF_X + ((size_t)b * 2 + (j - 2)) * 2048 + 1024 + 4 * tid) = val;
        }
    }

    if (tid < NN) {
        int n = tid;
        float s0 = s_s[n][0], s1 = s_s[n][1], s2 = s_s[n][2], s3 = s_s[n][3];
        if (n < NSEQ) {
            out[OFF_ATT1 + (size_t)b * 60 + n] = __expf(s0 - mm[0]) * linv[0];
            out[OFF_A11 + (size_t)b * 60 + n]  = __expf(s1 - mm[1]) * linv[1];
            out[OFF_A21 + (size_t)b * 60 + n]  = __expf(s3 - mm[3]) * linv[3];
        } else {
            int nn = n - NSEQ;
            out[OFF_ATT2 + (size_t)b * 60 + nn] = __expf(s2 - mm[2]) * linv[2];
            out[OFF_A12 + (size_t)b * 60 + nn]  = __expf(s1 - mm[1]) * linv[1];
            out[OFF_A22 + (size_t)b * 60 + nn]  = __expf(s3 - mm[3]) * linv[3];
        }
    }
}

// ---------------------------------------------------------------------------
extern "C" void kernel_launch(void* const* d_in, const int* in_sizes, int n_in,
                              void* d_out, int out_size)
{
    (void)in_sizes; (void)n_in; (void)out_size;
    const float* x1   = (const float*)d_in[0];
    const float* x2   = (const float*)d_in[1];
    const float* fc_w = (const float*)d_in[2];
    // d_in[3] = fc_b (constant per class: doesn't change argmax over n)
    const float* q_w  = (const float*)d_in[4];
    const float* q_b  = (const float*)d_in[5];
    float* out = (float*)d_out;

    k_split_w<<<1024, 256>>>(q_w);

    dim3 g1(BB, 2);
    k_select<<<g1, 256>>>(x1, x2, fc_w, out);

    cudaFuncSetAttribute(k_qm_mma, cudaFuncAttributeMaxDynamicSharedMemorySize, QM_SMEM);
    dim3 g2(8, 32);
    k_qm_mma<<<g2, 256, QM_SMEM>>>(q_b);

    k_attend<<<BB, 256>>>(x1, x2, out);
}

// round 4
// speedup vs baseline: 1.8009x; 1.1851x over previous
#include <cuda_runtime.h>
#include <cuda_bf16.h>
#include <math.h>
#include <stdint.h>

#define BB   1024
#define NSEQ 60
#define FF   1024
#define NN   120   // 2*NSEQ

// Output layout (flattened tuple, fp32):
// x(B,2,2048) o1(B,2,1024) o2 h1 h2 ATT1(B,60,1) ATT2 att11(B,60) att22 att12 att21
#define OFF_X    0ull
#define OFF_O1   4194304ull
#define OFF_O2   6291456ull
#define OFF_H1   8388608ull
#define OFF_H2   10485760ull
#define OFF_ATT1 12582912ull
#define OFF_ATT2 12644352ull
#define OFF_A11  12705792ull
#define OFF_A22  12767232ull
#define OFF_A12  12828672ull
#define OFF_A21  12890112ull

// Scratch
static __device__ __nv_bfloat16 g_thh[4096 * 1024];  // tanh(h) hi
static __device__ __nv_bfloat16 g_thl[4096 * 1024];  // tanh(h) lo
static __device__ __nv_bfloat16 g_qwh[1024 * 1024];  // q_w hi
static __device__ __nv_bfloat16 g_qwl[1024 * 1024];  // q_w lo
static __device__ float         g_qm[4096 * 1024];   // qm

typedef unsigned int uint32;
#define FULLW 0xffffffffu

__device__ __forceinline__ float dot4(float4 a, float4 b) {
    return a.x * b.x + a.y * b.y + a.z * b.z + a.w * b.w;
}

__device__ __forceinline__ void split4(float4 v, uint2& uh, uint2& ul) {
    __nv_bfloat16 h0 = __float2bfloat16_rn(v.x);
    __nv_bfloat16 h1 = __float2bfloat16_rn(v.y);
    __nv_bfloat16 h2 = __float2bfloat16_rn(v.z);
    __nv_bfloat16 h3 = __float2bfloat16_rn(v.w);
    __nv_bfloat16 l0 = __float2bfloat16_rn(v.x - __bfloat162float(h0));
    __nv_bfloat16 l1 = __float2bfloat16_rn(v.y - __bfloat162float(h1));
    __nv_bfloat16 l2 = __float2bfloat16_rn(v.z - __bfloat162float(h2));
    __nv_bfloat16 l3 = __float2bfloat16_rn(v.w - __bfloat162float(h3));
    uh.x = ((uint32)__bfloat16_as_ushort(h1) << 16) | __bfloat16_as_ushort(h0);
    uh.y = ((uint32)__bfloat16_as_ushort(h3) << 16) | __bfloat16_as_ushort(h2);
    ul.x = ((uint32)__bfloat16_as_ushort(l1) << 16) | __bfloat16_as_ushort(l0);
    ul.y = ((uint32)__bfloat16_as_ushort(l3) << 16) | __bfloat16_as_ushort(l2);
}

__device__ __forceinline__ void cpa16(uint32 dst, const void* src) {
    asm volatile("cp.async.cg.shared.global [%0], [%1], 16;" :: "r"(dst), "l"(src));
}

// ---------------------------------------------------------------------------
// K0: split q_w into bf16 hi/lo
// ---------------------------------------------------------------------------
__global__ __launch_bounds__(256) void k_split_w(const float* __restrict__ qw)
{
    int idx = blockIdx.x * 256 + threadIdx.x;
    float4 v = ((const float4*)qw)[idx];
    uint2 uh, ul;
    split4(v, uh, ul);
    *(uint2*)(g_qwh + 4 * (size_t)idx) = uh;
    *(uint2*)(g_qwl + 4 * (size_t)idx) = ul;
}

// ---------------------------------------------------------------------------
// K1: logits = x @ fc_w.T ; argmax ; gather h ; write h + split(tanh(h))
// ---------------------------------------------------------------------------
__global__ __launch_bounds__(256) void k_select(
    const float* __restrict__ x1, const float* __restrict__ x2,
    const float* __restrict__ fc_w, float* __restrict__ out)
{
    const int b = blockIdx.x;
    const int which = blockIdx.y;
    const float* x = which ? x2 : x1;
    const float4* x4 = (const float4*)(x + (size_t)b * NSEQ * FF);

    const int tid = threadIdx.x;
    const int w = tid >> 5, lane = tid & 31;

    __shared__ float4 s_fw[512];
    __shared__ float s_log[2][64];
    __shared__ int s_idx[2];

    const float4* fw4 = (const float4*)fc_w;
    s_fw[tid] = fw4[tid];
    s_fw[tid + 256] = fw4[tid + 256];
    __syncthreads();

    for (int n = w; n < NSEQ; n += 8) {
        const float4* row = x4 + n * 256;
        float p0 = 0.f, p1 = 0.f;
#pragma unroll
        for (int i = 0; i < 8; i++) {
            float4 v = row[lane + 32 * i];
            p0 += dot4(v, s_fw[lane + 32 * i]);
            p1 += dot4(v, s_fw[256 + lane + 32 * i]);
        }
#pragma unroll
        for (int off = 16; off; off >>= 1) {
            p0 += __shfl_down_sync(FULLW, p0, off);
            p1 += __shfl_down_sync(FULLW, p1, off);
        }
        if (lane == 0) { s_log[0][n] = p0; s_log[1][n] = p1; }
    }
    __syncthreads();

    if (tid < 2) {
        float best = s_log[tid][0];
        int bi = 0;
        for (int n = 1; n < NSEQ; n++) {
            float v = s_log[tid][n];
            if (v > best) { best = v; bi = n; }
        }
        s_idx[tid] = bi;
    }
    __syncthreads();

    const int i0 = s_idx[0], i1 = s_idx[1];
    float4* h4 = (float4*)(out + (which ? OFF_H2 : OFF_H1) + (size_t)b * 2 * FF);
    const size_t row0 = ((size_t)b * 4 + which * 2) * FF;

    float4 v = x4[i0 * 256 + tid];
    h4[tid] = v;
    float4 t0 = make_float4(tanhf(v.x), tanhf(v.y), tanhf(v.z), tanhf(v.w));
    uint2 uh, ul;
    split4(t0, uh, ul);
    *(uint2*)(g_thh + row0 + 4 * tid) = uh;
    *(uint2*)(g_thl + row0 + 4 * tid) = ul;

    v = x4[i1 * 256 + tid];
    h4[256 + tid] = v;
    float4 t1 = make_float4(tanhf(v.x), tanhf(v.y), tanhf(v.z), tanhf(v.w));
    split4(t1, uh, ul);
    *(uint2*)(g_thh + row0 + FF + 4 * tid) = uh;
    *(uint2*)(g_thl + row0 + FF + 4 * tid) = ul;
}

// ---------------------------------------------------------------------------
// K2: qm = tanh(h) @ q_w.T + q_b via 3xBF16 tensor-core GEMM
// 3-stage cp.async pipeline (dynamic smem), wait_group 1, 2 CTAs/SM.
// ---------------------------------------------------------------------------
#define QM_STAGE_BYTES 24576
#define QM_ROWB 48
#define QM_AH 0
#define QM_AL 6144
#define QM_BH 12288
#define QM_BL 18432
#define QM_SMEM (3 * QM_STAGE_BYTES)

__device__ __forceinline__ void ldsm4(uint32* r, uint32 addr) {
    asm volatile("ldmatrix.sync.aligned.m8n8.x4.shared.b16 {%0,%1,%2,%3}, [%4];"
                 : "=r"(r[0]), "=r"(r[1]), "=r"(r[2]), "=r"(r[3]) : "r"(addr));
}
__device__ __forceinline__ void mma_bf16(float* c, const uint32* a, uint32 b0, uint32 b1) {
    asm volatile(
        "mma.sync.aligned.m16n8k16.row.col.f32.bf16.bf16.f32 "
        "{%0,%1,%2,%3}, {%4,%5,%6,%7}, {%8,%9}, {%0,%1,%2,%3};"
        : "+f"(c[0]), "+f"(c[1]), "+f"(c[2]), "+f"(c[3])
        : "r"(a[0]), "r"(a[1]), "r"(a[2]), "r"(a[3]), "r"(b0), "r"(b1));
}

__global__ __launch_bounds__(256, 2) void k_qm_mma(const float* __restrict__ qb)
{
    extern __shared__ __align__(128) unsigned char smem[];

    const int tid = threadIdx.x;
    const int lane = tid & 31;
    const int wid = tid >> 5;
    const int warp_m = wid >> 1;
    const int warp_n = wid & 1;
    const int m0 = blockIdx.y * 128;
    const int n0 = blockIdx.x * 128;

    const uint32 sbase = (uint32)__cvta_generic_to_shared(smem);

    const int lrow = tid >> 1;
    const int lch  = tid & 1;
    const uint32 ldst = lrow * QM_ROWB + lch * 16;

    const int ag = lane >> 3;
    const uint32 a_off = (warp_m * 32 + (lane & 7) + (ag & 1) * 8) * QM_ROWB + (ag >> 1) * 16;
    const uint32 b_off = (warp_n * 64 + (lane & 7) + ((lane >> 4) & 1) * 8) * QM_ROWB
                         + ((lane >> 3) & 1) * 16;

    float c[2][8][4];
#pragma unroll
    for (int mt = 0; mt < 2; mt++)
#pragma unroll
        for (int nt = 0; nt < 8; nt++)
#pragma unroll
            for (int i = 0; i < 4; i++) c[mt][nt][i] = 0.f;

#pragma unroll
    for (int s = 0; s < 2; s++) {
        const uint32 st = s * QM_STAGE_BYTES;
        const size_t ka = (size_t)(m0 + lrow) * 1024 + s * 16 + lch * 8;
        const size_t kb = (size_t)(n0 + lrow) * 1024 + s * 16 + lch * 8;
        cpa16(sbase + st + QM_AH + ldst, g_thh + ka);
        cpa16(sbase + st + QM_AL + ldst, g_thl + ka);
        cpa16(sbase + st + QM_BH + ldst, g_qwh + kb);
        cpa16(sbase + st + QM_BL + ldst, g_qwl + kb);
        asm volatile("cp.async.commit_group;");
    }

    int cur_s = 0, nxt_s = 2;
    for (int it = 0; it < 64; it++) {
        const uint32 cur = cur_s * QM_STAGE_BYTES;
        asm volatile("cp.async.wait_group 1;");
        __syncthreads();

        if (it < 62) {
            const uint32 nxt = nxt_s * QM_STAGE_BYTES;
            const size_t ka = (size_t)(m0 + lrow) * 1024 + (it + 2) * 16 + lch * 8;
            const size_t kb = (size_t)(n0 + lrow) * 1024 + (it + 2) * 16 + lch * 8;
            cpa16(sbase + nxt + QM_AH + ldst, g_thh + ka);
            cpa16(sbase + nxt + QM_AL + ldst, g_thl + ka);
            cpa16(sbase + nxt + QM_BH + ldst, g_qwh + kb);
            cpa16(sbase + nxt + QM_BL + ldst, g_qwl + kb);
            asm volatile("cp.async.commit_group;");
        } else {
            asm volatile("cp.async.commit_group;");
        }

        uint32 ah[2][4], al[2][4];
#pragma unroll
        for (int mt = 0; mt < 2; mt++) {
            ldsm4(ah[mt], sbase + cur + QM_AH + a_off + mt * 16 * QM_ROWB);
            ldsm4(al[mt], sbase + cur + QM_AL + a_off + mt * 16 * QM_ROWB);
        }
#pragma unroll
        for (int p = 0; p < 4; p++) {
            uint32 bh[4], bl[4];
            ldsm4(bh, sbase + cur + QM_BH + b_off + p * 16 * QM_ROWB);
            ldsm4(bl, sbase + cur + QM_BL + b_off + p * 16 * QM_ROWB);
#pragma unroll
            for (int mt = 0; mt < 2; mt++) {
                mma_bf16(c[mt][2 * p],     ah[mt], bh[0], bh[1]);
                mma_bf16(c[mt][2 * p],     ah[mt], bl[0], bl[1]);
                mma_bf16(c[mt][2 * p],     al[mt], bh[0], bh[1]);
                mma_bf16(c[mt][2 * p + 1], ah[mt], bh[2], bh[3]);
                mma_bf16(c[mt][2 * p + 1], ah[mt], bl[2], bl[3]);
                mma_bf16(c[mt][2 * p + 1], al[mt], bh[2], bh[3]);
            }
        }
        cur_s = (cur_s == 2) ? 0 : cur_s + 1;
        nxt_s = (nxt_s == 2) ? 0 : nxt_s + 1;
    }

#pragma unroll
    for (int mt = 0; mt < 2; mt++) {
        const int mg = m0 + warp_m * 32 + mt * 16 + (lane >> 2);
#pragma unroll
        for (int nt = 0; nt < 8; nt++) {
            const int ng = n0 + warp_n * 64 + nt * 8 + 2 * (lane & 3);
            const float b0 = __ldg(qb + ng), b1 = __ldg(qb + ng + 1);
            *(float2*)(g_qm + (size_t)mg * 1024 + ng) =
                make_float2(c[mt][nt][0] + b0, c[mt][nt][1] + b1);
            *(float2*)(g_qm + (size_t)(mg + 8) * 1024 + ng) =
                make_float2(c[mt][nt][2] + b0, c[mt][nt][3] + b1);
        }
    }
}

// ---------------------------------------------------------------------------
// K3: fused attention, plain (no-max) softmax — scores are O(1) so exp is
// safe; removes the serial max/rescale chain. cp.async 4-stage smem pipeline
// for L rows; 3 CTAs/SM.
// smem layout (dynamic): [0,65536) L stages; [65536,67456) s_s; [67456,67968) s_red
// ---------------------------------------------------------------------------
#define AT_L    0
#define AT_SS   65536
#define AT_RED  67456
#define AT_SMEM 67968

__global__ __launch_bounds__(256, 3) void k_attend(
    const float* __restrict__ x1, const float* __restrict__ x2,
    float* __restrict__ out)
{
    extern __shared__ __align__(16) unsigned char smem[];
    float4* s_L  = (float4*)(smem + AT_L);             // [stage][row][256]
    float (*s_s)[4] = (float (*)[4])(smem + AT_SS);    // [120][4]
    float (*s_red)[16] = (float (*)[16])(smem + AT_RED); // [8][16]

    const int b = blockIdx.x;
    const int tid = threadIdx.x;
    const int w = tid >> 5, lane = tid & 31;
    const uint32 sL = (uint32)__cvta_generic_to_shared(s_L);

    const float* x1b = x1 + (size_t)b * NSEQ * FF;
    const float* x2b = x2 + (size_t)b * NSEQ * FF;
    const float4* qmg = (const float4*)(g_qm + (size_t)b * 4 * FF);

    // issue one stage: 4 rows of batch bt into stage bt&3
#define AT_ISSUE(bt)                                                          \
    {                                                                         \
        const int _st = (bt) & 3;                                             \
        _Pragma("unroll")                                                     \
        for (int _r = 0; _r < 4; _r++) {                                      \
            int _n = (bt) * 4 + _r;                                           \
            const float* _src = (_n < NSEQ) ? (x1b + (size_t)_n * FF)         \
                                            : (x2b + (size_t)(_n - NSEQ) * FF); \
            cpa16(sL + ((_st * 4 + _r) * 256 + tid) * 16, _src + 4 * tid);    \
        }                                                                     \
        asm volatile("cp.async.commit_group;");                               \
    }

    AT_ISSUE(0); AT_ISSUE(1); AT_ISSUE(2);

    float4 qm[4];
#pragma unroll
    for (int j = 0; j < 4; j++) qm[j] = qmg[j * 256 + tid];

    float4 o[4];
#pragma unroll
    for (int j = 0; j < 4; j++) o[j] = make_float4(0.f, 0.f, 0.f, 0.f);

    float l_run = 0.f;                  // per-lane, column lane&3
    const float scale = 0.03125f;

    for (int bt = 0; bt < 30; bt++) {
        asm volatile("cp.async.wait_group 2;");
        __syncthreads();                // barrier 1: stage data + s_red reuse

        const int st = bt & 3;
        float4 rv[4];
#pragma unroll
        for (int r = 0; r < 4; r++) rv[r] = s_L[(st * 4 + r) * 256 + tid];

        if (bt + 3 < 30) { AT_ISSUE(bt + 3); }
        else { asm volatile("cp.async.commit_group;"); }

        float p[16];
#pragma unroll
        for (int r = 0; r < 4; r++)
#pragma unroll
            for (int j = 0; j < 4; j++) p[r * 4 + j] = dot4(rv[r], qm[j]);

        // multi-value butterfly: value v ends on lanes 2v, 2v+1
#pragma unroll
        for (int v = 0; v < 16; v++) p[v] += __shfl_xor_sync(FULLW, p[v], 16);
        float q8[8];
#pragma unroll
        for (int v = 0; v < 8; v++) q8[v] = (lane & 16) ? p[v + 8] : p[v];
#pragma unroll
        for (int v = 0; v < 8; v++) q8[v] += __shfl_xor_sync(FULLW, q8[v], 8);
        float q4[4];
#pragma unroll
        for (int v = 0; v < 4; v++) q4[v] = (lane & 8) ? q8[v + 4] : q8[v];
#pragma unroll
        for (int v = 0; v < 4; v++) q4[v] += __shfl_xor_sync(FULLW, q4[v], 4);
        float q2[2];
#pragma unroll
        for (int v = 0; v < 2; v++) q2[v] = (lane & 4) ? q4[v + 2] : q4[v];
#pragma unroll
        for (int v = 0; v < 2; v++) q2[v] += __shfl_xor_sync(FULLW, q2[v], 2);
        float q1 = (lane & 2) ? q2[1] : q2[0];
        q1 += __shfl_xor_sync(FULLW, q1, 1);

        if (!(lane & 1)) s_red[w][lane >> 1] = q1;
        __syncthreads();                // barrier 2: partials visible

        float v16 = 0.f;
        if (lane < 16) {
#pragma unroll
            for (int ww = 0; ww < 8; ww++) v16 += s_red[ww][lane];
            v16 *= scale;
        }
        if (w == 0 && lane < 16) s_s[bt * 4 + (lane >> 2)][lane & 3] = v16;

        const int j = lane & 3;
        float t0 = __shfl_sync(FULLW, v16, j);
        float t1 = __shfl_sync(FULLW, v16, 4 + j);
        float t2 = __shfl_sync(FULLW, v16, 8 + j);
        float t3 = __shfl_sync(FULLW, v16, 12 + j);

        float w0 = __expf(t0);
        float w1 = __expf(t1);
        float w2 = __expf(t2);
        float w3 = __expf(t3);
        l_run += (w0 + w1) + (w2 + w3);

#pragma unroll
        for (int r = 0; r < 4; r++) {
            float wr = (r == 0) ? w0 : (r == 1) ? w1 : (r == 2) ? w2 : w3;
            float wa = __shfl_sync(FULLW, wr, 0);
            float wb = __shfl_sync(FULLW, wr, 1);
            float wc = __shfl_sync(FULLW, wr, 2);
            float wd = __shfl_sync(FULLW, wr, 3);
            o[0].x += wa * rv[r].x; o[0].y += wa * rv[r].y; o[0].z += wa * rv[r].z; o[0].w += wa * rv[r].w;
            o[1].x += wb * rv[r].x; o[1].y += wb * rv[r].y; o[1].z += wb * rv[r].z; o[1].w += wb * rv[r].w;
            o[2].x += wc * rv[r].x; o[2].y += wc * rv[r].y; o[2].z += wc * rv[r].z; o[2].w += wc * rv[r].w;
            o[3].x += wd * rv[r].x; o[3].y += wd * rv[r].y; o[3].z += wd * rv[r].z; o[3].w += wd * rv[r].w;
        }
    }
    __syncthreads();

    float linv[4];
#pragma unroll
    for (int j = 0; j < 4; j++) linv[j] = 1.f / __shfl_sync(FULLW, l_run, j);

#pragma unroll
    for (int j = 0; j < 4; j++) {
        float4 val;
        val.x = 0.9f * o[j].x * linv[j] + 0.1f * qm[j].x;
        val.y = 0.9f * o[j].y * linv[j] + 0.1f * qm[j].y;
        val.z = 0.9f * o[j].z * linv[j] + 0.1f * qm[j].z;
        val.w = 0.9f * o[j].w * linv[j] + 0.1f * qm[j].w;
        if (j < 2) {
            *(float4*)(out + OFF_O1 + ((size_t)b * 2 + j) * FF + 4 * tid) = val;
            *(float4*)(out + OFF_X + ((size_t)b * 2 + j) * 2048 + 4 * tid) = val;
        } else {
            *(float4*)(out + OFF_O2 + ((size_t)b * 2 + (j - 2)) * FF + 4 * tid) = val;
            *(float4*)(out + OFF_X + ((size_t)b * 2 + (j - 2)) * 2048 + 1024 + 4 * tid) = val;
        }
    }

    if (tid < NN) {
        int n = tid;
        float s0 = s_s[n][0], s1 = s_s[n][1], s2 = s_s[n][2], s3 = s_s[n][3];
        if (n < NSEQ) {
            out[OFF_ATT1 + (size_t)b * 60 + n] = __expf(s0) * linv[0];
            out[OFF_A11 + (size_t)b * 60 + n]  = __expf(s1) * linv[1];
            out[OFF_A21 + (size_t)b * 60 + n]  = __expf(s3) * linv[3];
        } else {
            int nn = n - NSEQ;
            out[OFF_ATT2 + (size_t)b * 60 + nn] = __expf(s2) * linv[2];
            out[OFF_A12 + (size_t)b * 60 + nn]  = __expf(s1) * linv[1];
            out[OFF_A22 + (size_t)b * 60 + nn]  = __expf(s3) * linv[3];
        }
    }
#undef AT_ISSUE
}

// ---------------------------------------------------------------------------
extern "C" void kernel_launch(void* const* d_in, const int* in_sizes, int n_in,
                              void* d_out, int out_size)
{
    (void)in_sizes; (void)n_in; (void)out_size;
    const float* x1   = (const float*)d_in[0];
    const float* x2   = (const float*)d_in[1];
    const float* fc_w = (const float*)d_in[2];
    // d_in[3] = fc_b (constant per class: doesn't change argmax over n)
    const float* q_w  = (const float*)d_in[4];
    const float* q_b  = (const float*)d_in[5];
    float* out = (float*)d_out;

    k_split_w<<<1024, 256>>>(q_w);

    dim3 g1(BB, 2);
    k_select<<<g1, 256>>>(x1, x2, fc_w, out);

    cudaFuncSetAttribute(k_qm_mma, cudaFuncAttributeMaxDynamicSharedMemorySize, QM_SMEM);
    dim3 g2(8, 32);
    k_qm_mma<<<g2, 256, QM_SMEM>>>(q_b);

    cudaFuncSetAttribute(k_attend, cudaFuncAttributeMaxDynamicSharedMemorySize, AT_SMEM);
    k_attend<<<BB, 256, AT_SMEM>>>(x1, x2, out);
}